// round 2
// baseline (speedup 1.0000x reference)
#include <cuda_runtime.h>

#define NPTS 100000
#define CDIM 64

// Scratch (device globals — no allocations allowed in kernel_launch)
__device__ float g_q[NPTS * CDIM];
__device__ float g_k[NPTS * CDIM];
__device__ float g_v[NPTS * CDIM];

typedef unsigned long long u64;

// d = a * b + d (elementwise on packed f32x2) — FFMA2, only reachable via PTX
__device__ __forceinline__ void fma2(u64& d, u64 a, u64 b) {
    asm("fma.rn.f32x2 %0, %1, %2, %0;" : "+l"(d) : "l"(a), "l"(b));
}
__device__ __forceinline__ void unpack2(u64 v, float& lo, float& hi) {
    asm("mov.b64 {%0, %1}, %2;" : "=f"(lo), "=f"(hi) : "l"(v));
}

// ---------------------------------------------------------------------------
// Kernel 1: fused q/k/v projection.  [N,64] @ [64,192] (Wq|Wk|Wv columns).
// Persistent blocks. W fully resident in smem in k-pair-interleaved layout:
//   sW2[((k>>1)*96 + p)*4 + (k&1)*2 + (c&1)]  for col-pair p = c3>>1
// so one LDS.128 = {w(2kk,c),w(2kk,c+1),w(2kk+1,c),w(2kk+1,c+1)} = 2 FFMA2 ops.
// feats tile stored DUPLICATED: sFd[(row*64+k)*2 + {0,1}] = f(row,k) so one
// broadcast LDS.128 = {f,f,f',f'} = two dup multiplier pairs, zero MOVs.
// Thread tile: 8 rows x 3 col-pairs (one pair per matrix).
// ---------------------------------------------------------------------------
extern __shared__ float qkv_smem[];

__global__ __launch_bounds__(256, 2) void qkv_kernel(
    const float* __restrict__ feats,
    const float* __restrict__ Wq,
    const float* __restrict__ Wk,
    const float* __restrict__ Wv,
    int N, int ntiles)
{
    float* sFd = qkv_smem;          // 64*64*2 = 8192 floats (32 KB)
    float* sW2 = qkv_smem + 8192;   // 64*192  = 12288 floats (48 KB)

    const int tid = threadIdx.x;
    const int ty  = tid >> 5;   // 0..7 : row group (8 rows each)
    const int tx  = tid & 31;   // 0..31: col pair within each matrix

    // ---- Load W once (k-pair-interleaved layout) ----
    {
        const float* Ws[3] = {Wq, Wk, Wv};
#pragma unroll
        for (int j = 0; j < 3; j++) {
            const float* W = Ws[j];
            for (int t = tid; t < 4096; t += 256) {
                int k = t >> 6, c = t & 63;
                int p = j * 32 + (c >> 1);
                sW2[((k >> 1) * 96 + p) * 4 + (k & 1) * 2 + (c & 1)] = W[t];
            }
        }
    }
    __syncthreads();

    for (int tile = blockIdx.x; tile < ntiles; tile += gridDim.x) {
        const int row0 = tile * 64;
        const int rows = min(64, N - row0);

        // ---- Load feats tile, duplicated ----
        if (rows == 64) {
            const float4* src = (const float4*)(feats + (size_t)row0 * 64);
#pragma unroll
            for (int t = 0; t < 4; t++) {
                int e = tid + 256 * t;          // float4 index: row=e>>4, c0=(e&15)*4
                float4 v = src[e];
                float* d = &sFd[((e >> 4) * 64 + (e & 15) * 4) * 2];
                *(float2*)(d + 0) = make_float2(v.x, v.x);
                *(float2*)(d + 2) = make_float2(v.y, v.y);
                *(float2*)(d + 4) = make_float2(v.z, v.z);
                *(float2*)(d + 6) = make_float2(v.w, v.w);
            }
        } else {
            for (int t = tid; t < 4096; t += 256) {
                int r = t >> 6, c = t & 63;
                float v = (r < rows) ? feats[(size_t)(row0 + r) * 64 + c] : 0.f;
                *(float2*)&sFd[(r * 64 + c) * 2] = make_float2(v, v);
            }
        }
        __syncthreads();

        u64 acc[8][3];
#pragma unroll
        for (int r = 0; r < 8; r++)
#pragma unroll
            for (int j = 0; j < 3; j++) acc[r][j] = 0ull;

#pragma unroll 2
        for (int kk = 0; kk < 32; kk++) {
            ulonglong2 f[8];
#pragma unroll
            for (int r = 0; r < 8; r++)
                f[r] = *(const ulonglong2*)&sFd[((ty * 8 + r) * 64 + kk * 2) * 2];
#pragma unroll
            for (int j = 0; j < 3; j++) {
                ulonglong2 w = *(const ulonglong2*)&sW2[(kk * 96 + j * 32 + tx) * 4];
#pragma unroll
                for (int r = 0; r < 8; r++) {
                    fma2(acc[r][j], w.x, f[r].x);
                    fma2(acc[r][j], w.y, f[r].y);
                }
            }
        }

#pragma unroll
        for (int r = 0; r < 8; r++) {
            int row = row0 + ty * 8 + r;
            if (row < N) {
                size_t off = (size_t)row * 64 + 2 * tx;
                float2 vq, vk, vv;
                unpack2(acc[r][0], vq.x, vq.y);
                unpack2(acc[r][1], vk.x, vk.y);
                unpack2(acc[r][2], vv.x, vv.y);
                *(float2*)&g_q[off] = vq;
                *(float2*)&g_k[off] = vk;
                *(float2*)&g_v[off] = vv;
            }
        }
        __syncthreads();   // protect sFd before next tile's load
    }
}

// ---------------------------------------------------------------------------
// Kernel 2: KNN attention + fused output projection.
// One thread per (point, head). Warp = 4 points x 8 heads: each 256B neighbor
// row is read fully coalesced. knn indices distributed via shuffle.
// Epilogue: the 8 threads of a point exchange their head outputs via shuffle
// and apply Wo (smem) + bo, writing the final output directly.
// ---------------------------------------------------------------------------
__global__ __launch_bounds__(256) void attn_kernel(
    const int* __restrict__ knn,
    const float* __restrict__ Wo,
    const float* __restrict__ bo,
    float* __restrict__ out,
    int N)
{
    __shared__ __align__(16) float sWo[64 * 64];
    {
        const float4* src = (const float4*)Wo;
        float4* dst = (float4*)sWo;
#pragma unroll
        for (int t = 0; t < 4; t++) dst[threadIdx.x + 256 * t] = src[threadIdx.x + 256 * t];
    }
    __syncthreads();

    const int g = blockIdx.x * 256 + threadIdx.x;
    int n = g >> 3;
    const int h = g & 7;
    const bool valid = (n < N);
    if (n >= N) n = N - 1;   // clamp: all lanes stay active for shuffles

    const int lane = threadIdx.x & 31;
    const int base = lane & 24;   // first lane of this point's 8-thread group

    // Each of the 8 threads holds 2 of the 16 neighbor indices
    const int my0 = knn[(size_t)n * 16 + h * 2];
    const int my1 = knn[(size_t)n * 16 + h * 2 + 1];

    const float* qp = g_q + (size_t)n * 64 + h * 8;
    const float4 q0 = *(const float4*)qp;
    const float4 q1 = *(const float4*)(qp + 4);

    int   idx[16];
    float s[16];
#pragma unroll
    for (int k = 0; k < 16; k++) {
        int v = (k & 1) ? my1 : my0;
        idx[k] = __shfl_sync(0xffffffffu, v, base + (k >> 1));
    }

#pragma unroll
    for (int k = 0; k < 16; k++) {
        const float* kp = g_k + (size_t)idx[k] * 64 + h * 8;
        const float4 a = *(const float4*)kp;
        const float4 b = *(const float4*)(kp + 4);
        float d = q0.x * a.x + q0.y * a.y + q0.z * a.z + q0.w * a.w
                + q1.x * b.x + q1.y * b.y + q1.z * b.z + q1.w * b.w;
        s[k] = d * 0.3535533905932738f;   // 1/sqrt(8)
    }

    // softmax over 16 neighbors (registers)
    float m = s[0];
#pragma unroll
    for (int k = 1; k < 16; k++) m = fmaxf(m, s[k]);
    float sum = 0.f;
#pragma unroll
    for (int k = 0; k < 16; k++) { s[k] = __expf(s[k] - m); sum += s[k]; }
    const float inv = 1.0f / sum;

    float o[8];
#pragma unroll
    for (int d = 0; d < 8; d++) o[d] = 0.f;
#pragma unroll
    for (int k = 0; k < 16; k++) {
        const float* vp = g_v + (size_t)idx[k] * 64 + h * 8;
        const float4 a = *(const float4*)vp;
        const float4 b = *(const float4*)(vp + 4);
        const float p = s[k];
        o[0] += p * a.x; o[1] += p * a.y; o[2] += p * a.z; o[3] += p * a.w;
        o[4] += p * b.x; o[5] += p * b.y; o[6] += p * b.z; o[7] += p * b.w;
    }
#pragma unroll
    for (int d = 0; d < 8; d++) o[d] *= inv;

    // ---- Fused output projection: out[n, h*8 .. h*8+7] ----
    float4 acc0, acc1;
    {
        const float4* bp = (const float4*)(bo + h * 8);
        acc0 = bp[0];
        acc1 = bp[1];
    }
#pragma unroll
    for (int src = 0; src < 8; src++) {
#pragma unroll
        for (int d = 0; d < 8; d++) {
            float aj = __shfl_sync(0xffffffffu, o[d], base + src);
            const float4* wp = (const float4*)&sWo[(src * 8 + d) * 64 + h * 8];
            float4 w0 = wp[0], w1 = wp[1];
            acc0.x += aj * w0.x; acc0.y += aj * w0.y;
            acc0.z += aj * w0.z; acc0.w += aj * w0.w;
            acc1.x += aj * w1.x; acc1.y += aj * w1.y;
            acc1.z += aj * w1.z; acc1.w += aj * w1.w;
        }
    }

    if (valid) {
        float* op = out + (size_t)n * 64 + h * 8;
        *(float4*)op       = acc0;
        *(float4*)(op + 4) = acc1;
    }
}

// ---------------------------------------------------------------------------
extern "C" void kernel_launch(void* const* d_in, const int* in_sizes, int n_in,
                              void* d_out, int out_size)
{
    const float* feats = (const float*)d_in[0];
    const int*   knn   = (const int*)d_in[1];
    const float* Wq    = (const float*)d_in[2];
    const float* Wk    = (const float*)d_in[3];
    const float* Wv    = (const float*)d_in[4];
    const float* Wo    = (const float*)d_in[5];
    const float* bo    = (const float*)d_in[6];
    float* out = (float*)d_out;

    const int N = in_sizes[0] / CDIM;
    const int ntiles = (N + 63) / 64;
    const int attn_blocks = (N * 8 + 255) / 256;
    const int qkv_smem_bytes = (8192 + 12288) * 4;   // 80 KB

    cudaFuncSetAttribute(qkv_kernel, cudaFuncAttributeMaxDynamicSharedMemorySize,
                         qkv_smem_bytes);

    qkv_kernel<<<296, 256, qkv_smem_bytes>>>(feats, Wq, Wk, Wv, N, ntiles);
    attn_kernel<<<attn_blocks, 256>>>(knn, Wo, bo, out, N);
}

// round 3
// speedup vs baseline: 1.7632x; 1.7632x over previous
#include <cuda_runtime.h>
#include <cuda_fp16.h>

#define NPTS 100000
#define CDIM 64

// Scratch (device globals — no allocations allowed in kernel_launch)
__device__ float  g_q[NPTS * CDIM];
__device__ __half g_k[NPTS * CDIM];
__device__ __half g_v[NPTS * CDIM];
__device__ float  g_a[NPTS * CDIM];

typedef unsigned long long u64;

// d = a * b + d (elementwise on packed f32x2) — FFMA2, only reachable via PTX
__device__ __forceinline__ void fma2(u64& d, u64 a, u64 b) {
    asm("fma.rn.f32x2 %0, %1, %2, %0;" : "+l"(d) : "l"(a), "l"(b));
}
__device__ __forceinline__ void unpack2(u64 v, float& lo, float& hi) {
    asm("mov.b64 {%0, %1}, %2;" : "=f"(lo), "=f"(hi) : "l"(v));
}
__device__ __forceinline__ u64 pack2f(float lo, float hi) {
    u64 r;
    asm("mov.b64 %0, {%1, %2};" : "=l"(r) : "f"(lo), "f"(hi));
    return r;
}

// ---------------------------------------------------------------------------
// Kernel 1: fused q/k/v projection.  [N,64] @ [64,192] (Wq|Wk|Wv columns).
// Persistent blocks; W fully resident in smem (k-pair-interleaved so one
// LDS.128 = 2 FFMA2 weight pairs); feats tile duplicated so one broadcast
// LDS.128 = 2 ready multiplier pairs. q stored fp32, k/v stored fp16.
// ---------------------------------------------------------------------------
extern __shared__ float qkv_smem[];

__global__ __launch_bounds__(256, 2) void qkv_kernel(
    const float* __restrict__ feats,
    const float* __restrict__ Wq,
    const float* __restrict__ Wk,
    const float* __restrict__ Wv,
    int N, int ntiles)
{
    float* sFd = qkv_smem;          // 64*64*2 = 8192 floats (32 KB)
    float* sW2 = qkv_smem + 8192;   // 64*192  = 12288 floats (48 KB)

    const int tid = threadIdx.x;
    const int ty  = tid >> 5;   // 0..7 : row group (8 rows each)
    const int tx  = tid & 31;   // 0..31: col pair within each matrix

    // ---- Load W once (k-pair-interleaved layout) ----
    {
        const float* Ws[3] = {Wq, Wk, Wv};
#pragma unroll
        for (int j = 0; j < 3; j++) {
            const float* W = Ws[j];
            for (int t = tid; t < 4096; t += 256) {
                int k = t >> 6, c = t & 63;
                int p = j * 32 + (c >> 1);
                sW2[((k >> 1) * 96 + p) * 4 + (k & 1) * 2 + (c & 1)] = W[t];
            }
        }
    }
    __syncthreads();

    for (int tile = blockIdx.x; tile < ntiles; tile += gridDim.x) {
        const int row0 = tile * 64;
        const int rows = min(64, N - row0);

        // ---- Load feats tile, duplicated ----
        if (rows == 64) {
            const float4* src = (const float4*)(feats + (size_t)row0 * 64);
#pragma unroll
            for (int t = 0; t < 4; t++) {
                int e = tid + 256 * t;
                float4 v = src[e];
                float* d = &sFd[((e >> 4) * 64 + (e & 15) * 4) * 2];
                *(float2*)(d + 0) = make_float2(v.x, v.x);
                *(float2*)(d + 2) = make_float2(v.y, v.y);
                *(float2*)(d + 4) = make_float2(v.z, v.z);
                *(float2*)(d + 6) = make_float2(v.w, v.w);
            }
        } else {
            for (int t = tid; t < 4096; t += 256) {
                int r = t >> 6, c = t & 63;
                float v = (r < rows) ? feats[(size_t)(row0 + r) * 64 + c] : 0.f;
                *(float2*)&sFd[(r * 64 + c) * 2] = make_float2(v, v);
            }
        }
        __syncthreads();

        u64 acc[8][3];
#pragma unroll
        for (int r = 0; r < 8; r++)
#pragma unroll
            for (int j = 0; j < 3; j++) acc[r][j] = 0ull;

#pragma unroll 2
        for (int kk = 0; kk < 32; kk++) {
            ulonglong2 f[8];
#pragma unroll
            for (int r = 0; r < 8; r++)
                f[r] = *(const ulonglong2*)&sFd[((ty * 8 + r) * 64 + kk * 2) * 2];
#pragma unroll
            for (int j = 0; j < 3; j++) {
                ulonglong2 w = *(const ulonglong2*)&sW2[(kk * 96 + j * 32 + tx) * 4];
#pragma unroll
                for (int r = 0; r < 8; r++) {
                    fma2(acc[r][j], w.x, f[r].x);
                    fma2(acc[r][j], w.y, f[r].y);
                }
            }
        }

#pragma unroll
        for (int r = 0; r < 8; r++) {
            int row = row0 + ty * 8 + r;
            if (row < N) {
                size_t off = (size_t)row * 64 + 2 * tx;
                float2 vq, vk, vv;
                unpack2(acc[r][0], vq.x, vq.y);
                unpack2(acc[r][1], vk.x, vk.y);
                unpack2(acc[r][2], vv.x, vv.y);
                *(float2*)&g_q[off]  = vq;
                *(__half2*)&g_k[off] = __float22half2_rn(vk);
                *(__half2*)&g_v[off] = __float22half2_rn(vv);
            }
        }
        __syncthreads();
    }
}

// ---------------------------------------------------------------------------
// Kernel 2: KNN attention. One thread per (point, head).
// Warp = 4 points x 8 heads; neighbor rows are fp16 (128 B/row) so the 8-lane
// head group reads a row fully coalesced with ONE LDG.128 per lane.
// ---------------------------------------------------------------------------
__global__ __launch_bounds__(256) void attn_kernel(const int* __restrict__ knn, int N)
{
    const int g = blockIdx.x * 256 + threadIdx.x;
    int n = g >> 3;
    const int h = g & 7;
    const bool valid = (n < N);
    if (n >= N) n = N - 1;   // clamp: all lanes stay active for shuffles

    const int lane = threadIdx.x & 31;
    const int base = lane & 24;

    const int my0 = knn[(size_t)n * 16 + h * 2];
    const int my1 = knn[(size_t)n * 16 + h * 2 + 1];

    const float* qp = g_q + (size_t)n * 64 + h * 8;
    const float4 q0 = *(const float4*)qp;
    const float4 q1 = *(const float4*)(qp + 4);

    int   idx[16];
    float s[16];
#pragma unroll
    for (int k = 0; k < 16; k++) {
        int v = (k & 1) ? my1 : my0;
        idx[k] = __shfl_sync(0xffffffffu, v, base + (k >> 1));
    }

#pragma unroll
    for (int k = 0; k < 16; k++) {
        const __half2* kp = (const __half2*)(g_k + (size_t)idx[k] * 64 + h * 8);
        uint4 raw = *(const uint4*)kp;   // 8 halves
        float2 a0 = __half22float2(*(__half2*)&raw.x);
        float2 a1 = __half22float2(*(__half2*)&raw.y);
        float2 a2 = __half22float2(*(__half2*)&raw.z);
        float2 a3 = __half22float2(*(__half2*)&raw.w);
        float d = q0.x * a0.x + q0.y * a0.y + q0.z * a1.x + q0.w * a1.y
                + q1.x * a2.x + q1.y * a2.y + q1.z * a3.x + q1.w * a3.y;
        s[k] = d * 0.3535533905932738f;   // 1/sqrt(8)
    }

    // softmax over 16 neighbors (registers)
    float m = s[0];
#pragma unroll
    for (int k = 1; k < 16; k++) m = fmaxf(m, s[k]);
    float sum = 0.f;
#pragma unroll
    for (int k = 0; k < 16; k++) { s[k] = __expf(s[k] - m); sum += s[k]; }
    const float inv = 1.0f / sum;

    float o[8];
#pragma unroll
    for (int d = 0; d < 8; d++) o[d] = 0.f;
#pragma unroll
    for (int k = 0; k < 16; k++) {
        const __half2* vp = (const __half2*)(g_v + (size_t)idx[k] * 64 + h * 8);
        uint4 raw = *(const uint4*)vp;
        float2 a0 = __half22float2(*(__half2*)&raw.x);
        float2 a1 = __half22float2(*(__half2*)&raw.y);
        float2 a2 = __half22float2(*(__half2*)&raw.z);
        float2 a3 = __half22float2(*(__half2*)&raw.w);
        const float p = s[k];
        o[0] += p * a0.x; o[1] += p * a0.y; o[2] += p * a1.x; o[3] += p * a1.y;
        o[4] += p * a2.x; o[5] += p * a2.y; o[6] += p * a3.x; o[7] += p * a3.y;
    }

    if (valid) {
        float4 r0 = make_float4(o[0] * inv, o[1] * inv, o[2] * inv, o[3] * inv);
        float4 r1 = make_float4(o[4] * inv, o[5] * inv, o[6] * inv, o[7] * inv);
        float* op = g_a + (size_t)n * 64 + h * 8;
        *(float4*)op       = r0;
        *(float4*)(op + 4) = r1;
    }
}

// ---------------------------------------------------------------------------
// Kernel 3: output projection. [N,64] @ Wo[64,64] + bo. Register-tiled GEMM.
// ---------------------------------------------------------------------------
__global__ __launch_bounds__(256) void oproj_kernel(
    const float* __restrict__ Wo,
    const float* __restrict__ bo,
    float* __restrict__ out,
    int N)
{
    __shared__ __align__(16) float sF[64 * 64];
    __shared__ __align__(16) float sW[64 * 64];

    const int tid  = threadIdx.x;
    const int row0 = blockIdx.x * 64;

    {
        const float4* src = (const float4*)Wo;
        float4* dst = (float4*)sW;
#pragma unroll
        for (int t = 0; t < 4; t++) dst[tid + 256 * t] = src[tid + 256 * t];
    }
    if (row0 + 64 <= N) {
        const float4* src = (const float4*)(g_a + (size_t)row0 * 64);
        float4* dst = (float4*)sF;
#pragma unroll
        for (int t = 0; t < 4; t++) dst[tid + 256 * t] = src[tid + 256 * t];
    } else {
        for (int t = tid; t < 64 * 64; t += 256) {
            int r = t >> 6;
            sF[t] = (row0 + r < N) ? g_a[(size_t)(row0 + r) * 64 + (t & 63)] : 0.f;
        }
    }
    __syncthreads();

    const int ty = tid >> 5;
    const int tx = tid & 31;

    u64 acc[8];
#pragma unroll
    for (int r = 0; r < 8; r++) acc[r] = 0ull;

#pragma unroll 8
    for (int i = 0; i < 64; i++) {
        u64 w = *(const u64*)&sW[i * 64 + 2 * tx];
#pragma unroll
        for (int r = 0; r < 8; r++) {
            float fv = sF[(ty * 8 + r) * 64 + i];
            fma2(acc[r], w, pack2f(fv, fv));
        }
    }

    const float b0 = bo[2 * tx];
    const float b1 = bo[2 * tx + 1];
#pragma unroll
    for (int r = 0; r < 8; r++) {
        int row = row0 + ty * 8 + r;
        if (row < N) {
            float2 v;
            unpack2(acc[r], v.x, v.y);
            v.x += b0; v.y += b1;
            *(float2*)&out[(size_t)row * 64 + 2 * tx] = v;
        }
    }
}

// ---------------------------------------------------------------------------
extern "C" void kernel_launch(void* const* d_in, const int* in_sizes, int n_in,
                              void* d_out, int out_size)
{
    const float* feats = (const float*)d_in[0];
    const int*   knn   = (const int*)d_in[1];
    const float* Wq    = (const float*)d_in[2];
    const float* Wk    = (const float*)d_in[3];
    const float* Wv    = (const float*)d_in[4];
    const float* Wo    = (const float*)d_in[5];
    const float* bo    = (const float*)d_in[6];
    float* out = (float*)d_out;

    const int N = in_sizes[0] / CDIM;
    const int ntiles = (N + 63) / 64;
    const int attn_blocks = (N * 8 + 255) / 256;
    const int qkv_smem_bytes = (8192 + 12288) * 4;   // 80 KB

    cudaFuncSetAttribute(qkv_kernel, cudaFuncAttributeMaxDynamicSharedMemorySize,
                         qkv_smem_bytes);

    qkv_kernel<<<296, 256, qkv_smem_bytes>>>(feats, Wq, Wk, Wv, N, ntiles);
    attn_kernel<<<attn_blocks, 256>>>(knn, N);
    oproj_kernel<<<ntiles, 256>>>(Wo, bo, out, N);
}

// round 4
// speedup vs baseline: 1.7636x; 1.0003x over previous
#include <cuda_runtime.h>
#include <cuda_fp16.h>

#define NPTS 100000
#define CDIM 64

// Scratch (device globals — no allocations allowed in kernel_launch)
__device__ float  g_q[NPTS * CDIM];
__device__ __half g_k[NPTS * CDIM];
__device__ __half g_v[NPTS * CDIM];
__device__ float  g_a[NPTS * CDIM];

typedef unsigned long long u64;

// d = a * b + d (elementwise on packed f32x2) — FFMA2, only reachable via PTX
__device__ __forceinline__ void fma2(u64& d, u64 a, u64 b) {
    asm("fma.rn.f32x2 %0, %1, %2, %0;" : "+l"(d) : "l"(a), "l"(b));
}
__device__ __forceinline__ void unpack2(u64 v, float& lo, float& hi) {
    asm("mov.b64 {%0, %1}, %2;" : "=f"(lo), "=f"(hi) : "l"(v));
}
__device__ __forceinline__ u64 pack2f(float lo, float hi) {
    u64 r;
    asm("mov.b64 %0, {%1, %2};" : "=l"(r) : "f"(lo), "f"(hi));
    return r;
}

// ---------------------------------------------------------------------------
// Kernel 1: fused q/k/v projection.  [N,64] @ [64,192] (Wq|Wk|Wv columns).
// Persistent blocks; W fully resident in smem (k-pair-interleaved so one
// LDS.128 = 2 FFMA2 weight pairs); feats tile duplicated so one broadcast
// LDS.128 = 2 ready multiplier pairs. q stored fp32, k/v stored fp16.
// ---------------------------------------------------------------------------
extern __shared__ float qkv_smem[];

__global__ __launch_bounds__(256, 2) void qkv_kernel(
    const float* __restrict__ feats,
    const float* __restrict__ Wq,
    const float* __restrict__ Wk,
    const float* __restrict__ Wv,
    int N, int ntiles)
{
    float* sFd = qkv_smem;          // 64*64*2 = 8192 floats (32 KB)
    float* sW2 = qkv_smem + 8192;   // 64*192  = 12288 floats (48 KB)

    const int tid = threadIdx.x;
    const int ty  = tid >> 5;   // 0..7 : row group (8 rows each)
    const int tx  = tid & 31;   // 0..31: col pair within each matrix

    // ---- Load W once (k-pair-interleaved layout) ----
    {
        const float* Ws[3] = {Wq, Wk, Wv};
#pragma unroll
        for (int j = 0; j < 3; j++) {
            const float* W = Ws[j];
            for (int t = tid; t < 4096; t += 256) {
                int k = t >> 6, c = t & 63;
                int p = j * 32 + (c >> 1);
                sW2[((k >> 1) * 96 + p) * 4 + (k & 1) * 2 + (c & 1)] = W[t];
            }
        }
    }
    __syncthreads();

    for (int tile = blockIdx.x; tile < ntiles; tile += gridDim.x) {
        const int row0 = tile * 64;
        const int rows = min(64, N - row0);

        // ---- Load feats tile, duplicated ----
        if (rows == 64) {
            const float4* src = (const float4*)(feats + (size_t)row0 * 64);
#pragma unroll
            for (int t = 0; t < 4; t++) {
                int e = tid + 256 * t;
                float4 v = src[e];
                float* d = &sFd[((e >> 4) * 64 + (e & 15) * 4) * 2];
                *(float2*)(d + 0) = make_float2(v.x, v.x);
                *(float2*)(d + 2) = make_float2(v.y, v.y);
                *(float2*)(d + 4) = make_float2(v.z, v.z);
                *(float2*)(d + 6) = make_float2(v.w, v.w);
            }
        } else {
            for (int t = tid; t < 4096; t += 256) {
                int r = t >> 6, c = t & 63;
                float v = (r < rows) ? feats[(size_t)(row0 + r) * 64 + c] : 0.f;
                *(float2*)&sFd[(r * 64 + c) * 2] = make_float2(v, v);
            }
        }
        __syncthreads();

        u64 acc[8][3];
#pragma unroll
        for (int r = 0; r < 8; r++)
#pragma unroll
            for (int j = 0; j < 3; j++) acc[r][j] = 0ull;

#pragma unroll 2
        for (int kk = 0; kk < 32; kk++) {
            ulonglong2 f[8];
#pragma unroll
            for (int r = 0; r < 8; r++)
                f[r] = *(const ulonglong2*)&sFd[((ty * 8 + r) * 64 + kk * 2) * 2];
#pragma unroll
            for (int j = 0; j < 3; j++) {
                ulonglong2 w = *(const ulonglong2*)&sW2[(kk * 96 + j * 32 + tx) * 4];
#pragma unroll
                for (int r = 0; r < 8; r++) {
                    fma2(acc[r][j], w.x, f[r].x);
                    fma2(acc[r][j], w.y, f[r].y);
                }
            }
        }

#pragma unroll
        for (int r = 0; r < 8; r++) {
            int row = row0 + ty * 8 + r;
            if (row < N) {
                size_t off = (size_t)row * 64 + 2 * tx;
                float2 vq, vk, vv;
                unpack2(acc[r][0], vq.x, vq.y);
                unpack2(acc[r][1], vk.x, vk.y);
                unpack2(acc[r][2], vv.x, vv.y);
                *(float2*)&g_q[off]  = vq;
                *(__half2*)&g_k[off] = __float22half2_rn(vk);
                *(__half2*)&g_v[off] = __float22half2_rn(vv);
            }
        }
        __syncthreads();
    }
}

// ---------------------------------------------------------------------------
// Kernel 2: KNN attention. One thread per (point, head).
// Warp = 4 points x 8 heads; neighbor rows are fp16 (128 B/row) so the 8-lane
// head group reads a row fully coalesced with ONE LDG.128 per lane.
// ---------------------------------------------------------------------------
__global__ __launch_bounds__(256) void attn_kernel(const int* __restrict__ knn, int N)
{
    const int g = blockIdx.x * 256 + threadIdx.x;
    int n = g >> 3;
    const int h = g & 7;
    const bool valid = (n < N);
    if (n >= N) n = N - 1;   // clamp: all lanes stay active for shuffles

    const int lane = threadIdx.x & 31;
    const int base = lane & 24;

    const int my0 = knn[(size_t)n * 16 + h * 2];
    const int my1 = knn[(size_t)n * 16 + h * 2 + 1];

    const float* qp = g_q + (size_t)n * 64 + h * 8;
    const float4 q0 = *(const float4*)qp;
    const float4 q1 = *(const float4*)(qp + 4);

    int   idx[16];
    float s[16];
#pragma unroll
    for (int k = 0; k < 16; k++) {
        int v = (k & 1) ? my1 : my0;
        idx[k] = __shfl_sync(0xffffffffu, v, base + (k >> 1));
    }

#pragma unroll
    for (int k = 0; k < 16; k++) {
        const __half2* kp = (const __half2*)(g_k + (size_t)idx[k] * 64 + h * 8);
        uint4 raw = *(const uint4*)kp;   // 8 halves
        float2 a0 = __half22float2(*(__half2*)&raw.x);
        float2 a1 = __half22float2(*(__half2*)&raw.y);
        float2 a2 = __half22float2(*(__half2*)&raw.z);
        float2 a3 = __half22float2(*(__half2*)&raw.w);
        float d = q0.x * a0.x + q0.y * a0.y + q0.z * a1.x + q0.w * a1.y
                + q1.x * a2.x + q1.y * a2.y + q1.z * a3.x + q1.w * a3.y;
        s[k] = d * 0.3535533905932738f;   // 1/sqrt(8)
    }

    // softmax over 16 neighbors (registers)
    float m = s[0];
#pragma unroll
    for (int k = 1; k < 16; k++) m = fmaxf(m, s[k]);
    float sum = 0.f;
#pragma unroll
    for (int k = 0; k < 16; k++) { s[k] = __expf(s[k] - m); sum += s[k]; }
    const float inv = 1.0f / sum;

    float o[8];
#pragma unroll
    for (int d = 0; d < 8; d++) o[d] = 0.f;
#pragma unroll
    for (int k = 0; k < 16; k++) {
        const __half2* vp = (const __half2*)(g_v + (size_t)idx[k] * 64 + h * 8);
        uint4 raw = *(const uint4*)vp;
        float2 a0 = __half22float2(*(__half2*)&raw.x);
        float2 a1 = __half22float2(*(__half2*)&raw.y);
        float2 a2 = __half22float2(*(__half2*)&raw.z);
        float2 a3 = __half22float2(*(__half2*)&raw.w);
        const float p = s[k];
        o[0] += p * a0.x; o[1] += p * a0.y; o[2] += p * a1.x; o[3] += p * a1.y;
        o[4] += p * a2.x; o[5] += p * a2.y; o[6] += p * a3.x; o[7] += p * a3.y;
    }

    if (valid) {
        float4 r0 = make_float4(o[0] * inv, o[1] * inv, o[2] * inv, o[3] * inv);
        float4 r1 = make_float4(o[4] * inv, o[5] * inv, o[6] * inv, o[7] * inv);
        float* op = g_a + (size_t)n * 64 + h * 8;
        *(float4*)op       = r0;
        *(float4*)(op + 4) = r1;
    }
}

// ---------------------------------------------------------------------------
// Kernel 3: output projection. [N,64] @ Wo[64,64] + bo. Register-tiled GEMM.
// ---------------------------------------------------------------------------
__global__ __launch_bounds__(256) void oproj_kernel(
    const float* __restrict__ Wo,
    const float* __restrict__ bo,
    float* __restrict__ out,
    int N)
{
    __shared__ __align__(16) float sF[64 * 64];
    __shared__ __align__(16) float sW[64 * 64];

    const int tid  = threadIdx.x;
    const int row0 = blockIdx.x * 64;

    {
        const float4* src = (const float4*)Wo;
        float4* dst = (float4*)sW;
#pragma unroll
        for (int t = 0; t < 4; t++) dst[tid + 256 * t] = src[tid + 256 * t];
    }
    if (row0 + 64 <= N) {
        const float4* src = (const float4*)(g_a + (size_t)row0 * 64);
        float4* dst = (float4*)sF;
#pragma unroll
        for (int t = 0; t < 4; t++) dst[tid + 256 * t] = src[tid + 256 * t];
    } else {
        for (int t = tid; t < 64 * 64; t += 256) {
            int r = t >> 6;
            sF[t] = (row0 + r < N) ? g_a[(size_t)(row0 + r) * 64 + (t & 63)] : 0.f;
        }
    }
    __syncthreads();

    const int ty = tid >> 5;
    const int tx = tid & 31;

    u64 acc[8];
#pragma unroll
    for (int r = 0; r < 8; r++) acc[r] = 0ull;

#pragma unroll 8
    for (int i = 0; i < 64; i++) {
        u64 w = *(const u64*)&sW[i * 64 + 2 * tx];
#pragma unroll
        for (int r = 0; r < 8; r++) {
            float fv = sF[(ty * 8 + r) * 64 + i];
            fma2(acc[r], w, pack2f(fv, fv));
        }
    }

    const float b0 = bo[2 * tx];
    const float b1 = bo[2 * tx + 1];
#pragma unroll
    for (int r = 0; r < 8; r++) {
        int row = row0 + ty * 8 + r;
        if (row < N) {
            float2 v;
            unpack2(acc[r], v.x, v.y);
            v.x += b0; v.y += b1;
            *(float2*)&out[(size_t)row * 64 + 2 * tx] = v;
        }
    }
}

// ---------------------------------------------------------------------------
extern "C" void kernel_launch(void* const* d_in, const int* in_sizes, int n_in,
                              void* d_out, int out_size)
{
    const float* feats = (const float*)d_in[0];
    const int*   knn   = (const int*)d_in[1];
    const float* Wq    = (const float*)d_in[2];
    const float* Wk    = (const float*)d_in[3];
    const float* Wv    = (const float*)d_in[4];
    const float* Wo    = (const float*)d_in[5];
    const float* bo    = (const float*)d_in[6];
    float* out = (float*)d_out;

    const int N = in_sizes[0] / CDIM;
    const int ntiles = (N + 63) / 64;
    const int attn_blocks = (N * 8 + 255) / 256;
    const int qkv_smem_bytes = (8192 + 12288) * 4;   // 80 KB

    cudaFuncSetAttribute(qkv_kernel, cudaFuncAttributeMaxDynamicSharedMemorySize,
                         qkv_smem_bytes);

    qkv_kernel<<<296, 256, qkv_smem_bytes>>>(feats, Wq, Wk, Wv, N, ntiles);
    attn_kernel<<<attn_blocks, 256>>>(knn, N);
    oproj_kernel<<<ntiles, 256>>>(Wo, bo, out, N);
}